// round 13
// baseline (speedup 1.0000x reference)
#include <cuda_runtime.h>
#include <math.h>

#define NN   1024
#define OUTD 128
#define TJ   64
#define NT   16
#define RPAD 132
#define VPAD 132
#define OPAD 132
#define WST  65          // agg w smem row stride (odd => rh groups 16 banks apart)

#define ABSM 0x7FFFFFFF7FFFFFFFULL

typedef unsigned long long u64;

// ---- scratch ----
__device__ __align__(16) float g_L[NN * OUTD];
__device__ __align__(16) float g_R[NN * OUTD];
__device__ __align__(16) float g_V[NN * OUTD];
__device__ __align__(16) float g_aR[4 * NN];         // [h][j]
__device__ __align__(16) float g_w[NN * 4 * NN];     // [i][h][j] 16MB
__device__ __align__(16) float g_sinv[NN * 4];       // [i][h]

__constant__ __align__(16) float c_a[32];

// ---- f32x2 helpers ----
__device__ __forceinline__ u64 f2add(u64 a, u64 b) {
    u64 d; asm("add.rn.f32x2 %0,%1,%2;" : "=l"(d) : "l"(a), "l"(b)); return d;
}
__device__ __forceinline__ u64 f2fma(u64 a, u64 b, u64 c) {
    u64 d; asm("fma.rn.f32x2 %0,%1,%2,%3;" : "=l"(d) : "l"(a), "l"(b), "l"(c)); return d;
}
__device__ __forceinline__ u64 f2pack(float x, float y) {
    u64 d; asm("mov.b64 %0,{%1,%2};" : "=l"(d) : "f"(x), "f"(y)); return d;
}
__device__ __forceinline__ float2 f2unpack(u64 v) {
    float x, y; asm("mov.b64 {%0,%1},%2;" : "=f"(x), "=f"(y) : "l"(v));
    return make_float2(x, y);
}
__device__ __forceinline__ u64 a2c(int k) { return *(const u64*)&c_a[2 * k]; }

__device__ __forceinline__ unsigned smem_u32(const void* p)
{
    unsigned r;
    asm("{ .reg .u64 t; cvta.to.shared.u64 t, %1; cvt.u32.u64 %0, t; }"
        : "=r"(r) : "l"(p));
    return r;
}
__device__ __forceinline__ void cp16(float* dst, const float* src)
{
    unsigned d = smem_u32(dst);
    asm volatile("cp.async.cg.shared.global [%0], [%1], 16;" :: "r"(d), "l"(src));
}
__device__ __forceinline__ void cp4(float* dst, const float* src)
{
    unsigned d = smem_u32(dst);
    asm volatile("cp.async.ca.shared.global [%0], [%1], 4;" :: "r"(d), "l"(src));
}

// =====================================================================
// Kernel 1: C = h @ W, packed f32x2, BM=16, grid (64,3), 256 thr.
// mat==1 (W_r) also writes g_aR[h][row].
// =====================================================================
__global__ __launch_bounds__(256) void gemm_kernel(
    const float* __restrict__ H,
    const float* __restrict__ Wl,
    const float* __restrict__ Wr,
    const float* __restrict__ Wv)
{
    extern __shared__ float sm[];
    float* A_s = sm;              // [16][128]
    float* B_s = sm + 16 * 128;   // [128][128]

    const int tid = threadIdx.x;
    const int mat = blockIdx.y;
    const float* W = (mat == 0) ? Wl : ((mat == 1) ? Wr : Wv);
    float* C = (mat == 0) ? g_L : ((mat == 1) ? g_R : g_V);
    const int row0 = blockIdx.x * 16;

#pragma unroll
    for (int u = 0; u < 2; u++) {
        int id = tid + u * 256;
        int r = id >> 5, c4 = id & 31;
        *(float4*)&A_s[r * 128 + c4 * 4] =
            *(const float4*)&H[(row0 + r) * 128 + c4 * 4];
    }
#pragma unroll
    for (int u = 0; u < 16; u++) {
        int id = tid + u * 256;
        int r = id >> 5, c4 = id & 31;
        *(float4*)&B_s[r * 128 + c4 * 4] =
            *(const float4*)&W[r * OUTD + c4 * 4];
    }
    __syncthreads();

    const int ty = tid >> 5, tx = tid & 31;
    const int r0 = ty * 2;
    u64 c00 = 0ULL, c01 = 0ULL, c10 = 0ULL, c11 = 0ULL;

#pragma unroll 8
    for (int k = 0; k < 128; k++) {
        float a0 = A_s[(r0 + 0) * 128 + k];
        float a1 = A_s[(r0 + 1) * 128 + k];
        ulonglong2 b2 = *(const ulonglong2*)&B_s[k * 128 + tx * 4];
        u64 ap0 = f2pack(a0, a0);
        u64 ap1 = f2pack(a1, a1);
        c00 = f2fma(ap0, b2.x, c00); c01 = f2fma(ap0, b2.y, c01);
        c10 = f2fma(ap1, b2.x, c10); c11 = f2fma(ap1, b2.y, c11);
    }

    float2 u00 = f2unpack(c00), u01 = f2unpack(c01);
    float2 u10 = f2unpack(c10), u11 = f2unpack(c11);
    float a0c[4] = { u00.x, u00.y, u01.x, u01.y };
    float a1c[4] = { u10.x, u10.y, u11.x, u11.y };

    *(float4*)&C[(row0 + r0 + 0) * OUTD + tx * 4] =
        make_float4(a0c[0], a0c[1], a0c[2], a0c[3]);
    *(float4*)&C[(row0 + r0 + 1) * OUTD + tx * 4] =
        make_float4(a1c[0], a1c[1], a1c[2], a1c[3]);

    if (mat == 1) {
        const int hb = (tx & 7) * 4;
        float p0 = 0.f, p1 = 0.f;
#pragma unroll
        for (int c = 0; c < 4; c++) {
            float av = c_a[hb + c];
            p0 = fmaf(av, a0c[c], p0);
            p1 = fmaf(av, a1c[c], p1);
        }
#pragma unroll
        for (int o = 1; o < 8; o <<= 1) {
            p0 += __shfl_xor_sync(0xffffffffu, p0, o);
            p1 += __shfl_xor_sync(0xffffffffu, p1, o);
        }
        if ((tx & 7) == 0) {
            int h = tx >> 3;
            g_aR[h * NN + row0 + r0 + 0] = p0;
            g_aR[h * NN + row0 + r0 + 1] = p1;
        }
    }
}

// =====================================================================
// Kernel 2: SCORE. grid 256 x 512 thr (16 warps), 4 rows/block.
// 2 blocks/SM. Warp = (h = wid&3, rr = wid>>2) -> row = row0+rr.
// Lane = j (32 j per pass, jj=0,1 covers TJ=64). L register-resident.
// Writes w to g_w[i][h][j] (coalesced) and 1/sum to g_sinv.
// =====================================================================
// smem: R 2*64*132 = 16896 ; aR 2*256 = 512 -> 17408 floats (~70KB)
#define SSM_R  0
#define SSM_AR 16896
#define SCORE_SMEM_FLOATS 17408

__device__ __forceinline__ void score_prefetch(float* sm, int buf, int jb, int tid)
{
    float* Rd = sm + SSM_R + buf * TJ * RPAD;
#pragma unroll
    for (int u = 0; u < 4; u++) {
        int id = tid + u * 512; int r = id >> 5, c4 = id & 31;
        cp16(&Rd[r * RPAD + c4 * 4], &g_R[(jb + r) * OUTD + c4 * 4]);
    }
    if (tid < 64) {
        int h = tid >> 4, c4 = tid & 15;
        cp16(&sm[SSM_AR + buf * 256 + h * TJ + c4 * 4],
             &g_aR[h * NN + jb + c4 * 4]);
    }
}

__global__ __launch_bounds__(512, 2) void score_kernel(const int* __restrict__ adj)
{
    extern __shared__ float sm[];
    const int tid = threadIdx.x, lane = tid & 31, wid = tid >> 5;
    const int h  = wid & 3;
    const int rr = wid >> 2;               // 0..3
    const int row = blockIdx.x * 4 + rr;

    score_prefetch(sm, 0, 0, tid);
    asm volatile("cp.async.commit_group;" ::: "memory");

    // L register-resident: one row, head slice h (32 floats)
    u64 Lx[8], Ly[8];
    {
        const float* Lrow = &g_L[row * OUTD + h * 32];
#pragma unroll
        for (int k = 0; k < 8; k++) {
            ulonglong2 t2 = *(const ulonglong2*)&Lrow[k * 4];
            Lx[k] = t2.x; Ly[k] = t2.y;
        }
    }
    float lin;
    {
        u64 sa = 0ULL, sb = 0ULL;
#pragma unroll
        for (int k = 0; k < 8; k++) {
            sa = f2fma(a2c(2 * k), Lx[k], sa);
            sb = f2fma(a2c(2 * k + 1), Ly[k], sb);
        }
        float2 u = f2unpack(f2add(sa, sb));
        lin = 0.6f * (u.x + u.y);
    }

    float s_acc = 0.f;

    for (int t = 0; t < NT; t++) {
        const int rb = t & 1;
        asm volatile("cp.async.wait_group 0;" ::: "memory");
        __syncthreads();
        if (t + 1 < NT) {
            score_prefetch(sm, rb ^ 1, (t + 1) * TJ, tid);
            asm volatile("cp.async.commit_group;" ::: "memory");
        }

        const float* Rbase = sm + SSM_R + rb * TJ * RPAD;
        const float* aRb   = sm + SSM_AR + rb * 256 + h * TJ;
        const int*   arow  = adj + row * NN + t * TJ;
        float* wrow = &g_w[(row * 4 + h) * NN + t * TJ];

#pragma unroll
        for (int jj = 0; jj < 2; jj++) {
            const int jg = jj * 32 + lane;
            int av = arow[jg];
            const float* Rrow = Rbase + jg * RPAD + h * 32;
            u64 sa = 0ULL, sb = 0ULL;
#pragma unroll
            for (int k = 0; k < 8; k++) {
                ulonglong2 r2 = *(const ulonglong2*)&Rrow[k * 4];
                sa = f2fma(a2c(2 * k),     f2add(Lx[k], r2.x) & ABSM, sa);
                sb = f2fma(a2c(2 * k + 1), f2add(Ly[k], r2.y) & ABSM, sb);
            }
            float2 u = f2unpack(f2add(sa, sb));
            float e = fmaf(0.4f, u.x + u.y, lin + 0.6f * aRb[jg]);
            float w = av ? __expf(e) : 0.f;
            s_acc += w;
            wrow[jg] = w;
        }
    }

    // full-warp reduce (lane = j)
#pragma unroll
    for (int o = 1; o < 32; o <<= 1)
        s_acc += __shfl_xor_sync(0xffffffffu, s_acc, o);
    if (lane == 0)
        g_sinv[row * 4 + h] = 1.0f / s_acc;
}

// =====================================================================
// Kernel 3: AGG + LN. grid 128 x 512 thr, 8 rows/block.
// Warp (h=wid&3, jq=wid>>2) -> cols colb=h*32+jq*8.
// Lane (aj=lane>>1 j-index, rh=lane&1 -> rows rh*4..+3). acc 4x8.
// w staged gmem->smem [rowh][WST=65] via 4B cp.async (odd stride is
// NOT 16B-aligned; 4B copies always are). Reads conflict-free.
// =====================================================================
// smem: V 2*64*132=16896 ; W 2*32*65=4160 ; OUT 8*132=1056 -> 22112
#define ASM_V 0
#define ASM_W 16896
#define ASM_O (ASM_W + 2 * 32 * WST)
#define AGG_SMEM_FLOATS (ASM_O + 8 * OPAD)

__device__ __forceinline__ void agg_prefetch(float* sm, int buf, int jb,
                                             int tid, int row0)
{
    float* Vd = sm + ASM_V + buf * TJ * VPAD;
#pragma unroll
    for (int u = 0; u < 4; u++) {
        int id = tid + u * 512; int r = id >> 5, c4 = id & 31;
        cp16(&Vd[r * VPAD + c4 * 4], &g_V[(jb + r) * OUTD + c4 * 4]);
    }
    // w: 32 rowh (r*4+h) x 64 j ; 512 threads x 4 floats via 4B cp.async
    {
        int rowh = tid >> 4;      // 0..31 : r = rowh>>2, h = rowh&3
        int c4   = tid & 15;
        const float* srcp =
            &g_w[((row0 + (rowh >> 2)) * 4 + (rowh & 3)) * NN + jb + c4 * 4];
        float* dstp = &sm[ASM_W + buf * 32 * WST + rowh * WST + c4 * 4];
#pragma unroll
        for (int i = 0; i < 4; i++)
            cp4(dstp + i, srcp + i);
    }
}

__global__ __launch_bounds__(512) void agg_kernel(
    const float* __restrict__ ln_g,
    const float* __restrict__ ln_b,
    float* __restrict__ out)
{
    extern __shared__ float sm[];
    float* out_s = sm + ASM_O;

    const int tid = threadIdx.x, lane = tid & 31, wid = tid >> 5;
    const int h  = wid & 3;
    const int jq = wid >> 2;
    const int aj = lane >> 1;               // 0..15
    const int rh = lane & 1;
    const int colb = h * 32 + jq * 8;
    const int row0 = blockIdx.x * 8;

    agg_prefetch(sm, 0, 0, tid, row0);
    asm volatile("cp.async.commit_group;" ::: "memory");

    float acc[4][8];
#pragma unroll
    for (int r = 0; r < 4; r++)
#pragma unroll
        for (int c = 0; c < 8; c++) acc[r][c] = 0.f;

    for (int t = 0; t < NT; t++) {
        const int rb = t & 1;
        asm volatile("cp.async.wait_group 0;" ::: "memory");
        __syncthreads();
        if (t + 1 < NT) {
            agg_prefetch(sm, rb ^ 1, (t + 1) * TJ, tid, row0);
            asm volatile("cp.async.commit_group;" ::: "memory");
        }

        const float* Vb = sm + ASM_V + rb * TJ * VPAD;
        const float* wb = sm + ASM_W + rb * 32 * WST;

#pragma unroll
        for (int jj = 0; jj < 4; jj++) {
            int j = jj * 16 + aj;
            const float* vrow = &Vb[j * VPAD + colb];
            float4 v0 = *(const float4*)(vrow);
            float4 v1 = *(const float4*)(vrow + 4);
#pragma unroll
            for (int r = 0; r < 4; r++) {
                float w = wb[((rh * 4 + r) * 4 + h) * WST + j];
                acc[r][0] = fmaf(w, v0.x, acc[r][0]);
                acc[r][1] = fmaf(w, v0.y, acc[r][1]);
                acc[r][2] = fmaf(w, v0.z, acc[r][2]);
                acc[r][3] = fmaf(w, v0.w, acc[r][3]);
                acc[r][4] = fmaf(w, v1.x, acc[r][4]);
                acc[r][5] = fmaf(w, v1.y, acc[r][5]);
                acc[r][6] = fmaf(w, v1.z, acc[r][6]);
                acc[r][7] = fmaf(w, v1.w, acc[r][7]);
            }
        }
    }

    // reduce over 16 aj lanes (stride-2 groups)
#pragma unroll
    for (int r = 0; r < 4; r++)
#pragma unroll
        for (int c = 0; c < 8; c++) {
#pragma unroll
            for (int o = 2; o < 32; o <<= 1)
                acc[r][c] += __shfl_xor_sync(0xffffffffu, acc[r][c], o);
        }
    if (aj == 0) {
#pragma unroll
        for (int r = 0; r < 4; r++) {
            int row = rh * 4 + r;
            float inv = g_sinv[(row0 + row) * 4 + h];
            *(float4*)&out_s[row * OPAD + colb] =
                make_float4(acc[r][0] * inv, acc[r][1] * inv,
                            acc[r][2] * inv, acc[r][3] * inv);
            *(float4*)&out_s[row * OPAD + colb + 4] =
                make_float4(acc[r][4] * inv, acc[r][5] * inv,
                            acc[r][6] * inv, acc[r][7] * inv);
        }
    }
    __syncthreads();

    // LayerNorm + ReLU: warps 0..7, warp = row
    if (wid < 8) {
        float4 x = *(const float4*)&out_s[wid * OPAD + lane * 4];
        float ssum = x.x + x.y + x.z + x.w;
        float sqs  = x.x * x.x + x.y * x.y + x.z * x.z + x.w * x.w;
#pragma unroll
        for (int o = 16; o; o >>= 1) {
            ssum += __shfl_xor_sync(0xffffffffu, ssum, o);
            sqs  += __shfl_xor_sync(0xffffffffu, sqs, o);
        }
        float mu   = ssum * (1.0f / 128.0f);
        float var  = sqs * (1.0f / 128.0f) - mu * mu;
        float rstd = rsqrtf(var + 1e-5f);
        float4 g4 = *(const float4*)&ln_g[lane * 4];
        float4 b4 = *(const float4*)&ln_b[lane * 4];
        float y0 = fmaxf((x.x - mu) * rstd * g4.x + b4.x, 0.f);
        float y1 = fmaxf((x.y - mu) * rstd * g4.y + b4.y, 0.f);
        float y2 = fmaxf((x.z - mu) * rstd * g4.z + b4.z, 0.f);
        float y3 = fmaxf((x.w - mu) * rstd * g4.w + b4.w, 0.f);
        *(float4*)&out[(row0 + wid) * OUTD + lane * 4] =
            make_float4(y0, y1, y2, y3);
    }
}

// =====================================================================
extern "C" void kernel_launch(void* const* d_in, const int* in_sizes, int n_in,
                              void* d_out, int out_size)
{
    const float* h   = (const float*)d_in[0];
    const int*   adj = (const int*)d_in[1];
    const float* Wl  = (const float*)d_in[2];
    const float* Wr  = (const float*)d_in[3];
    const float* Wv  = (const float*)d_in[4];
    const float* a   = (const float*)d_in[5];
    const float* g   = (const float*)d_in[6];
    const float* b   = (const float*)d_in[7];
    float* out = (float*)d_out;

    const int gemm_smem  = (16 * 128 + 128 * 128) * (int)sizeof(float);  // 72KB
    const int score_smem = SCORE_SMEM_FLOATS * (int)sizeof(float);       // ~70KB
    const int agg_smem   = AGG_SMEM_FLOATS * (int)sizeof(float);         // ~88KB

    cudaFuncSetAttribute(gemm_kernel,
                         cudaFuncAttributeMaxDynamicSharedMemorySize, gemm_smem);
    cudaFuncSetAttribute(score_kernel,
                         cudaFuncAttributeMaxDynamicSharedMemorySize, score_smem);
    cudaFuncSetAttribute(agg_kernel,
                         cudaFuncAttributeMaxDynamicSharedMemorySize, agg_smem);

    cudaMemcpyToSymbolAsync(c_a, a, 32 * sizeof(float), 0,
                            cudaMemcpyDeviceToDevice, 0);

    gemm_kernel<<<dim3(64, 3), 256, gemm_smem>>>(h, Wl, Wr, Wv);
    score_kernel<<<256, 512, score_smem>>>(adj);
    agg_kernel<<<128, 512, agg_smem>>>(g, b, out);
}

// round 15
// speedup vs baseline: 1.2760x; 1.2760x over previous
#include <cuda_runtime.h>
#include <math.h>

#define NN   1024
#define OUTD 128
#define TJ   64
#define NT   16
#define RPAD 132
#define VPAD 132
#define LPAD 132
#define OPAD 132
#define WSTH 512        // w_s: h-stride = 64 j * 8 rows
#define WBUF 2048       // w_s buffer stride = 4 h * 512

#define ABSM 0x7FFFFFFF7FFFFFFFULL

typedef unsigned long long u64;

// ---- scratch ----
__device__ __align__(16) float g_L[NN * OUTD];
__device__ __align__(16) float g_R[NN * OUTD];
__device__ __align__(16) float g_V[NN * OUTD];
__device__ __align__(16) float g_aR[4 * NN];   // [h][j]

__constant__ __align__(16) float c_a[32];

// ---- f32x2 helpers ----
__device__ __forceinline__ u64 f2add(u64 a, u64 b) {
    u64 d; asm("add.rn.f32x2 %0,%1,%2;" : "=l"(d) : "l"(a), "l"(b)); return d;
}
__device__ __forceinline__ u64 f2fma(u64 a, u64 b, u64 c) {
    u64 d; asm("fma.rn.f32x2 %0,%1,%2,%3;" : "=l"(d) : "l"(a), "l"(b), "l"(c)); return d;
}
__device__ __forceinline__ u64 f2pack(float x, float y) {
    u64 d; asm("mov.b64 %0,{%1,%2};" : "=l"(d) : "f"(x), "f"(y)); return d;
}
__device__ __forceinline__ float2 f2unpack(u64 v) {
    float x, y; asm("mov.b64 {%0,%1},%2;" : "=f"(x), "=f"(y) : "l"(v));
    return make_float2(x, y);
}
__device__ __forceinline__ u64 a2c(int k) { return *(const u64*)&c_a[2 * k]; }

__device__ __forceinline__ unsigned smem_u32(const void* p)
{
    unsigned r;
    asm("{ .reg .u64 t; cvta.to.shared.u64 t, %1; cvt.u32.u64 %0, t; }"
        : "=r"(r) : "l"(p));
    return r;
}
__device__ __forceinline__ void cp16(float* dst, const float* src)
{
    unsigned d = smem_u32(dst);
    asm volatile("cp.async.cg.shared.global [%0], [%1], 16;" :: "r"(d), "l"(src));
}

// =====================================================================
// Kernel 1: C = h @ W, K-tiled + cp.async pipelined.
// BM=16, BN=128, KT=32 (4 tiles). grid (64,3), 256 thr, 40KB smem.
// mat==1 (W_r) also writes g_aR[h][row].
// =====================================================================
#define GKT 32
__global__ __launch_bounds__(256) void gemm_kernel(
    const float* __restrict__ H,
    const float* __restrict__ Wl,
    const float* __restrict__ Wr,
    const float* __restrict__ Wv)
{
    extern __shared__ float sm[];
    float* A_s = sm;               // [16][128]
    float* B_s = sm + 16 * 128;    // [2][32][128]

    const int tid = threadIdx.x;
    const int mat = blockIdx.y;
    const float* W = (mat == 0) ? Wl : ((mat == 1) ? Wr : Wv);
    float* C = (mat == 0) ? g_L : ((mat == 1) ? g_R : g_V);
    const int row0 = blockIdx.x * 16;

    // stage A (whole 16x128) + B tile 0, async
    {
#pragma unroll
        for (int u = 0; u < 2; u++) {
            int id = tid + u * 256;          // [0,512) float4
            int r = id >> 5, c4 = id & 31;
            cp16(&A_s[r * 128 + c4 * 4], &H[(row0 + r) * 128 + c4 * 4]);
        }
#pragma unroll
        for (int u = 0; u < 4; u++) {
            int id = tid + u * 256;          // [0,1024) float4
            int r = id >> 5, c4 = id & 31;
            cp16(&B_s[r * 128 + c4 * 4], &W[r * OUTD + c4 * 4]);
        }
        asm volatile("cp.async.commit_group;" ::: "memory");
    }

    const int ty = tid >> 5, tx = tid & 31;
    const int r0 = ty * 2;
    u64 c00 = 0ULL, c01 = 0ULL, c10 = 0ULL, c11 = 0ULL;

    for (int kt = 0; kt < 4; kt++) {
        asm volatile("cp.async.wait_group 0;" ::: "memory");
        __syncthreads();
        if (kt + 1 < 4) {
            float* Bd = B_s + ((kt + 1) & 1) * GKT * 128;
#pragma unroll
            for (int u = 0; u < 4; u++) {
                int id = tid + u * 256;
                int r = id >> 5, c4 = id & 31;
                cp16(&Bd[r * 128 + c4 * 4],
                     &W[((kt + 1) * GKT + r) * OUTD + c4 * 4]);
            }
            asm volatile("cp.async.commit_group;" ::: "memory");
        }
        const float* Bb = B_s + (kt & 1) * GKT * 128;
        const float* Arow0 = &A_s[(r0 + 0) * 128 + kt * GKT];
        const float* Arow1 = &A_s[(r0 + 1) * 128 + kt * GKT];
#pragma unroll
        for (int k = 0; k < GKT; k++) {
            float a0 = Arow0[k];
            float a1 = Arow1[k];
            ulonglong2 b2 = *(const ulonglong2*)&Bb[k * 128 + tx * 4];
            u64 ap0 = f2pack(a0, a0);
            u64 ap1 = f2pack(a1, a1);
            c00 = f2fma(ap0, b2.x, c00); c01 = f2fma(ap0, b2.y, c01);
            c10 = f2fma(ap1, b2.x, c10); c11 = f2fma(ap1, b2.y, c11);
        }
    }

    float2 u00 = f2unpack(c00), u01 = f2unpack(c01);
    float2 u10 = f2unpack(c10), u11 = f2unpack(c11);
    float a0c[4] = { u00.x, u00.y, u01.x, u01.y };
    float a1c[4] = { u10.x, u10.y, u11.x, u11.y };

    *(float4*)&C[(row0 + r0 + 0) * OUTD + tx * 4] =
        make_float4(a0c[0], a0c[1], a0c[2], a0c[3]);
    *(float4*)&C[(row0 + r0 + 1) * OUTD + tx * 4] =
        make_float4(a1c[0], a1c[1], a1c[2], a1c[3]);

    if (mat == 1) {
        const int hb = (tx & 7) * 4;
        float p0 = 0.f, p1 = 0.f;
#pragma unroll
        for (int c = 0; c < 4; c++) {
            float av = c_a[hb + c];
            p0 = fmaf(av, a0c[c], p0);
            p1 = fmaf(av, a1c[c], p1);
        }
#pragma unroll
        for (int o = 1; o < 8; o <<= 1) {
            p0 += __shfl_xor_sync(0xffffffffu, p0, o);
            p1 += __shfl_xor_sync(0xffffffffu, p1, o);
        }
        if ((tx & 7) == 0) {
            int h = tx >> 3;
            g_aR[h * NN + row0 + r0 + 0] = p0;
            g_aR[h * NN + row0 + r0 + 1] = p1;
        }
    }
}

// =====================================================================
// Kernel 2: 128 blocks x 512 threads (16 warps), 8 rows/block, TJ=64.
// Pipelined: agg lags score by 1 tile, ONE barrier per tile.
// w_s layout [h][j][8 rows]: score STS.128; agg LDS.128 + packed FFMA2.
// =====================================================================
// smem layout (floats)
#define SM_R  0
#define SM_V  (SM_R + 2 * TJ * RPAD)        // 16896
#define SM_AR (SM_V + 3 * TJ * VPAD)        // 42240
#define SM_W  (SM_AR + 2 * 256)             // 42752
#define SM_L  (SM_W + 2 * WBUF)             // 46848
#define SM_SP (SM_L + 8 * LPAD)             // 47904
#define SM_O  (SM_SP + 128)                 // 48032
#define GAT_SMEM_FLOATS (SM_O + 8 * OPAD)   // 49088 (~196KB)

__device__ __forceinline__ void prefetch_tile(float* sm, int rbuf, int vbuf,
                                              int jb, int tid)
{
    float* Rd = sm + SM_R + rbuf * TJ * RPAD;
    float* Vd = sm + SM_V + vbuf * TJ * VPAD;
#pragma unroll
    for (int u = 0; u < 4; u++) {
        int id = tid + u * 512; int r = id >> 5, c4 = id & 31;
        cp16(&Rd[r * RPAD + c4 * 4], &g_R[(jb + r) * OUTD + c4 * 4]);
    }
#pragma unroll
    for (int u = 0; u < 4; u++) {
        int id = tid + u * 512; int r = id >> 5, c4 = id & 31;
        cp16(&Vd[r * VPAD + c4 * 4], &g_V[(jb + r) * OUTD + c4 * 4]);
    }
    if (tid < 64) {
        int h = tid >> 4, c4 = tid & 15;
        cp16(&sm[SM_AR + rbuf * 256 + h * TJ + c4 * 4],
             &g_aR[h * NN + jb + c4 * 4]);
    }
}

__global__ __launch_bounds__(512, 1) void gat_kernel(
    const int* __restrict__ adj,
    const float* __restrict__ ln_g,
    const float* __restrict__ ln_b,
    float* __restrict__ out)
{
    extern __shared__ float sm[];
    float* w_s   = sm + SM_W;
    float* L_s   = sm + SM_L;
    float* sp_s  = sm + SM_SP;
    float* out_s = sm + SM_O;

    const int tid = threadIdx.x, lane = tid & 31, wid = tid >> 5;
    const int h  = wid & 3;
    const int jq = wid >> 2;
    const int jg = jq * 16 + (lane >> 1);   // score j in tile
    const int rh = lane & 1;                // row half (both roles)
    const int aj = lane >> 1;               // agg j-lane 0..15
    const int colb = h * 32 + jq * 8;       // agg col base (8 cols)
    const int row0 = blockIdx.x * 8;

    // prologue: prefetch tile 0, stage L
    prefetch_tile(sm, 0, 0, 0, tid);
    asm volatile("cp.async.commit_group;" ::: "memory");
    if (tid < 256) {
        int r = tid >> 5, c4 = tid & 31;
        *(float4*)&L_s[r * LPAD + c4 * 4] =
            *(const float4*)&g_L[(row0 + r) * OUTD + c4 * 4];
    }
    __syncthreads();   // L_s ready

    // lin[ii] = 0.6 * (a . L[row, h-slice])
    float lin[4];
#pragma unroll
    for (int ii = 0; ii < 4; ii++) {
        const float* Lrow = &L_s[(rh * 4 + ii) * LPAD + h * 32];
        u64 sa = 0ULL, sb = 0ULL;
#pragma unroll
        for (int k = 0; k < 8; k++) {
            ulonglong2 l2 = *(const ulonglong2*)&Lrow[k * 4];
            sa = f2fma(a2c(2 * k), l2.x, sa);
            sb = f2fma(a2c(2 * k + 1), l2.y, sb);
        }
        float2 u = f2unpack(f2add(sa, sb));
        lin[ii] = 0.6f * (u.x + u.y);
    }

    // adj for tile 0
    int av[4];
#pragma unroll
    for (int ii = 0; ii < 4; ii++)
        av[ii] = adj[(row0 + rh * 4 + ii) * NN + jg];

    float s_acc[4] = { 0.f, 0.f, 0.f, 0.f };
    u64 acc[4][4];                            // agg: 4 rows x 8 cols packed
#pragma unroll
    for (int r = 0; r < 4; r++)
#pragma unroll
        for (int c = 0; c < 4; c++) acc[r][c] = 0ULL;

    for (int t = 0; t < NT; t++) {
        const int rb = t & 1;

        asm volatile("cp.async.wait_group 0;" ::: "memory");
        __syncthreads();   // tile t data ready; w[t-1] visible; old bufs free

        if (t + 1 < NT) {
            prefetch_tile(sm, rb ^ 1, (t + 1) % 3, (t + 1) * TJ, tid);
            asm volatile("cp.async.commit_group;" ::: "memory");
        }
        int avn[4];
        if (t + 1 < NT) {
#pragma unroll
            for (int ii = 0; ii < 4; ii++)
                avn[ii] = adj[(row0 + rh * 4 + ii) * NN + (t + 1) * TJ + jg];
        }

        // ========== AGG (tile t-1): vector w LDS + packed FFMA2 ==========
        if (t > 0) {
            const float* Vb = sm + SM_V + ((t - 1) % 3) * TJ * VPAD;
            const float* wb = w_s + ((t - 1) & 1) * WBUF + h * WSTH + rh * 4;
#pragma unroll
            for (int jj = 0; jj < 4; jj++) {
                int j = jj * 16 + aj;
                float4 wv = *(const float4*)&wb[j * 8];       // 4 rows' w
                const float* vrow = &Vb[j * VPAD + colb];
                ulonglong2 v0 = *(const ulonglong2*)(vrow);
                ulonglong2 v1 = *(const ulonglong2*)(vrow + 4);
                u64 wp0 = f2pack(wv.x, wv.x);
                u64 wp1 = f2pack(wv.y, wv.y);
                u64 wp2 = f2pack(wv.z, wv.z);
                u64 wp3 = f2pack(wv.w, wv.w);
                acc[0][0] = f2fma(wp0, v0.x, acc[0][0]);
                acc[0][1] = f2fma(wp0, v0.y, acc[0][1]);
                acc[0][2] = f2fma(wp0, v1.x, acc[0][2]);
                acc[0][3] = f2fma(wp0, v1.y, acc[0][3]);
                acc[1][0] = f2fma(wp1, v0.x, acc[1][0]);
                acc[1][1] = f2fma(wp1, v0.y, acc[1][1]);
                acc[1][2] = f2fma(wp1, v1.x, acc[1][2]);
                acc[1][3] = f2fma(wp1, v1.y, acc[1][3]);
                acc[2][0] = f2fma(wp2, v0.x, acc[2][0]);
                acc[2][1] = f2fma(wp2, v0.y, acc[2][1]);
                acc[2][2] = f2fma(wp2, v1.x, acc[2][2]);
                acc[2][3] = f2fma(wp2, v1.y, acc[2][3]);
                acc[3][0] = f2fma(wp3, v0.x, acc[3][0]);
                acc[3][1] = f2fma(wp3, v0.y, acc[3][1]);
                acc[3][2] = f2fma(wp3, v1.x, acc[3][2]);
                acc[3][3] = f2fma(wp3, v1.y, acc[3][3]);
            }
        }

        // ================= SCORE (tile t) =================
        {
            const float* Rrow = sm + SM_R + rb * TJ * RPAD + jg * RPAD + h * 32;
            float* wb = w_s + rb * WBUF;
            u64 sa[4], sb[4];
#pragma unroll
            for (int ii = 0; ii < 4; ii++) { sa[ii] = 0ULL; sb[ii] = 0ULL; }
#pragma unroll
            for (int k = 0; k < 8; k++) {
                ulonglong2 r2 = *(const ulonglong2*)&Rrow[k * 4];
#pragma unroll
                for (int ii = 0; ii < 4; ii++) {
                    const ulonglong2 l2 = *(const ulonglong2*)
                        &L_s[(rh * 4 + ii) * LPAD + h * 32 + k * 4];
                    sa[ii] = f2fma(a2c(2 * k),
                                   f2add(l2.x, r2.x) & ABSM, sa[ii]);
                    sb[ii] = f2fma(a2c(2 * k + 1),
                                   f2add(l2.y, r2.y) & ABSM, sb[ii]);
                }
            }
            float ar6 = 0.6f * sm[SM_AR + rb * 256 + h * TJ + jg];
            float w4[4];
#pragma unroll
            for (int ii = 0; ii < 4; ii++) {
                float2 u = f2unpack(f2add(sa[ii], sb[ii]));
                float e = fmaf(0.4f, u.x + u.y, lin[ii] + ar6);
                float w = av[ii] ? __expf(e) : 0.f;
                s_acc[ii] += w;
                w4[ii] = w;
            }
            *(float4*)&wb[h * WSTH + jg * 8 + rh * 4] =
                make_float4(w4[0], w4[1], w4[2], w4[3]);
        }
#pragma unroll
        for (int ii = 0; ii < 4; ii++) av[ii] = avn[ii];
    }

    // drain: agg for the last tile
    __syncthreads();
    {
        const float* Vb = sm + SM_V + ((NT - 1) % 3) * TJ * VPAD;
        const float* wb = w_s + ((NT - 1) & 1) * WBUF + h * WSTH + rh * 4;
#pragma unroll
        for (int jj = 0; jj < 4; jj++) {
            int j = jj * 16 + aj;
            float4 wv = *(const float4*)&wb[j * 8];
            const float* vrow = &Vb[j * VPAD + colb];
            ulonglong2 v0 = *(const ulonglong2*)(vrow);
            ulonglong2 v1 = *(const ulonglong2*)(vrow + 4);
            u64 wp0 = f2pack(wv.x, wv.x);
            u64 wp1 = f2pack(wv.y, wv.y);
            u64 wp2 = f2pack(wv.z, wv.z);
            u64 wp3 = f2pack(wv.w, wv.w);
            acc[0][0] = f2fma(wp0, v0.x, acc[0][0]);
            acc[0][1] = f2fma(wp0, v0.y, acc[0][1]);
            acc[0][2] = f2fma(wp0, v1.x, acc[0][2]);
            acc[0][3] = f2fma(wp0, v1.y, acc[0][3]);
            acc[1][0] = f2fma(wp1, v0.x, acc[1][0]);
            acc[1][1] = f2fma(wp1, v0.y, acc[1][1]);
            acc[1][2] = f2fma(wp1, v1.x, acc[1][2]);
            acc[1][3] = f2fma(wp1, v1.y, acc[1][3]);
            acc[2][0] = f2fma(wp2, v0.x, acc[2][0]);
            acc[2][1] = f2fma(wp2, v0.y, acc[2][1]);
            acc[2][2] = f2fma(wp2, v1.x, acc[2][2]);
            acc[2][3] = f2fma(wp2, v1.y, acc[2][3]);
            acc[3][0] = f2fma(wp3, v0.x, acc[3][0]);
            acc[3][1] = f2fma(wp3, v0.y, acc[3][1]);
            acc[3][2] = f2fma(wp3, v1.x, acc[3][2]);
            acc[3][3] = f2fma(wp3, v1.y, acc[3][3]);
        }
    }

    // ---- score sums: reduce over the 16 j-lanes (stride-2 groups) ----
#pragma unroll
    for (int ii = 0; ii < 4; ii++) {
#pragma unroll
        for (int o = 2; o < 32; o <<= 1)
            s_acc[ii] += __shfl_xor_sync(0xffffffffu, s_acc[ii], o);
    }
    if ((lane >> 1) == 0) {
#pragma unroll
        for (int ii = 0; ii < 4; ii++)
            sp_s[jq * 32 + (rh * 4 + ii) * 4 + h] = s_acc[ii];
    }
    __syncthreads();

    // ---- agg reduce over 16 aj lanes ----
#pragma unroll
    for (int r = 0; r < 4; r++)
#pragma unroll
        for (int c = 0; c < 4; c++) {
#pragma unroll
            for (int o = 2; o < 32; o <<= 1) {
                u64 other = __shfl_xor_sync(0xffffffffu, acc[r][c], o);
                acc[r][c] = f2add(acc[r][c], other);
            }
        }
    if (aj == 0) {
#pragma unroll
        for (int r = 0; r < 4; r++) {
            int row = rh * 4 + r;
            float s = sp_s[0 * 32 + row * 4 + h] + sp_s[1 * 32 + row * 4 + h]
                    + sp_s[2 * 32 + row * 4 + h] + sp_s[3 * 32 + row * 4 + h];
            float inv = 1.0f / s;
            float2 t0 = f2unpack(acc[r][0]);
            float2 t1 = f2unpack(acc[r][1]);
            float2 t2 = f2unpack(acc[r][2]);
            float2 t3 = f2unpack(acc[r][3]);
            *(float4*)&out_s[row * OPAD + colb] =
                make_float4(t0.x * inv, t0.y * inv, t1.x * inv, t1.y * inv);
            *(float4*)&out_s[row * OPAD + colb + 4] =
                make_float4(t2.x * inv, t2.y * inv, t3.x * inv, t3.y * inv);
        }
    }
    __syncthreads();

    // ---- LayerNorm + ReLU: warps 0..7, warp = row ----
    if (wid < 8) {
        float4 x = *(const float4*)&out_s[wid * OPAD + lane * 4];
        float ssum = x.x + x.y + x.z + x.w;
        float sqs  = x.x * x.x + x.y * x.y + x.z * x.z + x.w * x.w;
#pragma unroll
        for (int o = 16; o; o >>= 1) {
            ssum += __shfl_xor_sync(0xffffffffu, ssum, o);
            sqs  += __shfl_xor_sync(0xffffffffu, sqs, o);
        }
        float mu   = ssum * (1.0f / 128.0f);
        float var  = sqs * (1.0f / 128.0f) - mu * mu;
        float rstd = rsqrtf(var + 1e-5f);
        float4 g4 = *(const float4*)&ln_g[lane * 4];
        float4 b4 = *(const float4*)&ln_b[lane * 4];
        float y0 = fmaxf((x.x - mu) * rstd * g4.x + b4.x, 0.f);
        float y1 = fmaxf((x.y - mu) * rstd * g4.y + b4.y, 0.f);
        float y2 = fmaxf((x.z - mu) * rstd * g4.z + b4.z, 0.f);
        float y3 = fmaxf((x.w - mu) * rstd * g4.w + b4.w, 0.f);
        *(float4*)&out[(row0 + wid) * OUTD + lane * 4] =
            make_float4(y0, y1, y2, y3);
    }
}

// =====================================================================
extern "C" void kernel_launch(void* const* d_in, const int* in_sizes, int n_in,
                              void* d_out, int out_size)
{
    const float* h   = (const float*)d_in[0];
    const int*   adj = (const int*)d_in[1];
    const float* Wl  = (const float*)d_in[2];
    const float* Wr  = (const float*)d_in[3];
    const float* Wv  = (const float*)d_in[4];
    const float* a   = (const float*)d_in[5];
    const float* g   = (const float*)d_in[6];
    const float* b   = (const float*)d_in[7];
    float* out = (float*)d_out;

    const int gemm_smem = (16 * 128 + 2 * GKT * 128) * (int)sizeof(float); // 40KB
    const int gat_smem  = GAT_SMEM_FLOATS * (int)sizeof(float);            // ~196KB

    cudaFuncSetAttribute(gemm_kernel,
                         cudaFuncAttributeMaxDynamicSharedMemorySize, gemm_smem);
    cudaFuncSetAttribute(gat_kernel,
                         cudaFuncAttributeMaxDynamicSharedMemorySize, gat_smem);

    cudaMemcpyToSymbolAsync(c_a, a, 32 * sizeof(float), 0,
                            cudaMemcpyDeviceToDevice, 0);

    gemm_kernel<<<dim3(64, 3), 256, gemm_smem>>>(h, Wl, Wr, Wv);
    gat_kernel<<<128, 512, gat_smem>>>(adj, g, b, out);
}